// round 1
// baseline (speedup 1.0000x reference)
#include <cuda_runtime.h>

#define BB 8
#define NN 2048
#define DD 128
#define MM 128
#define ITERS 50
#define ROWS 64
#define NTHREADS 256

// scratch (allocation-free rule: __device__ globals)
__device__ float gMinv[BB * MM * MM];       // 512 KB
__device__ float gP[BB * NN * MM];          // 8 MB

// ---- packed f32x2 helpers (ptxas won't emit FFMA2 from C++) ----
__device__ __forceinline__ unsigned long long ffma2(unsigned long long a,
                                                    unsigned long long b,
                                                    unsigned long long c) {
    unsigned long long d;
    asm("fma.rn.f32x2 %0, %1, %2, %3;" : "=l"(d) : "l"(a), "l"(b), "l"(c));
    return d;
}
__device__ __forceinline__ unsigned long long pack2(float x) {
    union { unsigned long long u; float2 f; } c;
    c.f = make_float2(x, x);
    return c.u;
}
__device__ __forceinline__ float2 unpack2(unsigned long long v) {
    union { unsigned long long u; float2 f; } c;
    c.u = v;
    return c.f;
}

// ============================================================================
// Kernel 1: per batch, build M = I + (2/m^2) V V^T and invert in-place
// (Gauss-Jordan, no pivoting: M is SPD and ~identity). 8 blocks x 256 thr.
// smem: sV[128*129] + sA[128*129] + rowk[128]
// ============================================================================
__global__ __launch_bounds__(NTHREADS, 1) void k_minv(const float* __restrict__ gV) {
    extern __shared__ float smem[];
    float* sV = smem;                 // 128*129
    float* sA = smem + 128 * 129;     // 128*129
    float* rowk = sA + 128 * 129;     // 128
    const int b = blockIdx.x;
    const int t = threadIdx.x;

    for (int idx = t; idx < 128 * 128; idx += NTHREADS)
        sV[(idx >> 7) * 129 + (idx & 127)] = gV[b * 16384 + idx];
    __syncthreads();

    // M: thread t -> row i = t&127, col block jb = (t>>7)*64
    {
        const int i = t & 127;
        const int jb = (t >> 7) * 64;
        float acc[64];
#pragma unroll
        for (int jj = 0; jj < 64; jj++) acc[jj] = 0.0f;
        for (int d = 0; d < 128; d++) {
            float vi = sV[i * 129 + d];
#pragma unroll
            for (int jj = 0; jj < 64; jj++) acc[jj] += vi * sV[(jb + jj) * 129 + d];
        }
        const float s = 2.0f / 16384.0f;  // 2 * (1/m)^2
#pragma unroll
        for (int jj = 0; jj < 64; jj++) {
            int j = jb + jj;
            sA[i * 129 + j] = s * acc[jj] + ((i == j) ? 1.0f : 0.0f);
        }
    }
    __syncthreads();

    // in-place Gauss-Jordan: after loop, sA holds M^{-1}
    const int rr = t >> 1;
    const int c0 = (t & 1) << 6;
    for (int k = 0; k < 128; k++) {
        if (t < 128) {
            float pv = sA[k * 129 + k];
            float ip = 1.0f / pv;
            rowk[t] = (t == k) ? ip : sA[k * 129 + t] * ip;
        }
        float f = sA[rr * 129 + k];   // old value, read before writes
        __syncthreads();
        if (rr == k) {
            for (int j = 0; j < 64; j++) sA[k * 129 + c0 + j] = rowk[c0 + j];
        } else {
            for (int j = 0; j < 64; j++) {
                int c = c0 + j;
                float ov = (c == k) ? 0.0f : sA[rr * 129 + c];
                sA[rr * 129 + c] = ov - f * rowk[c];
            }
        }
        __syncthreads();
    }

    for (int idx = t; idx < 16384; idx += NTHREADS)
        gMinv[b * 16384 + idx] = sA[(idx >> 7) * 129 + (idx & 127)];
}

// ============================================================================
// Kernel 2: P[b,n,m'] = -(2/m) * sum_d V[m',d] Q[n,d] + lambda/m
// grid 256 (b*32 + tile), 256 thr. smem: sVt[128*128] ([d][m]) + sQ[64*129]
// ============================================================================
__global__ __launch_bounds__(NTHREADS, 1) void k_prep(const float* __restrict__ gQ,
                                                      const float* __restrict__ gV) {
    extern __shared__ float smem[];
    float* sVt = smem;               // [d][m] 128*128
    float* sQ = smem + 16384;        // 64*129
    const int blk = blockIdx.x;
    const int b = blk >> 5;
    const int row0 = (blk & 31) * ROWS;
    const int t = threadIdx.x;

    for (int idx = t; idx < 16384; idx += NTHREADS) {
        int m = idx >> 7, d = idx & 127;
        sVt[d * 128 + m] = gV[b * 16384 + idx];
    }
    for (int idx = t; idx < ROWS * 128; idx += NTHREADS) {
        int rl = idx >> 7, d = idx & 127;
        sQ[rl * 129 + d] = gQ[(b * NN + row0 + rl) * 128 + d];
    }
    __syncthreads();

    const int r = t & 63;
    const int i0 = (t >> 6) * 32;
    unsigned long long acc[16];
#pragma unroll
    for (int q = 0; q < 16; q++) acc[q] = 0ULL;
#pragma unroll 4
    for (int d = 0; d < 128; d++) {
        unsigned long long q2 = pack2(sQ[r * 129 + d]);
        const ulonglong2* pm = (const ulonglong2*)(sVt + d * 128 + i0);
#pragma unroll
        for (int q = 0; q < 8; q++) {
            ulonglong2 mv = pm[q];
            acc[2 * q] = ffma2(mv.x, q2, acc[2 * q]);
            acc[2 * q + 1] = ffma2(mv.y, q2, acc[2 * q + 1]);
        }
    }
    float* outp = gP + (b * NN + row0 + r) * 128 + i0;
    const float cP = -2.0f / 128.0f;      // -(2/m)
    const float cL = 0.1f / 128.0f;       // lambda/m
#pragma unroll
    for (int q = 0; q < 16; q++) {
        float2 v = unpack2(acc[q]);
        outp[2 * q] = cP * v.x + cL;
        outp[2 * q + 1] = cP * v.y + cL;
    }
}

// ============================================================================
// Kernel 3: 50 ADMM iterations + threshold + output GEMM, all fused.
// grid 256 (b*32 + tile), 256 thr. Thread owns (row r, 32 i's); z,u,P in regs.
// smem: sMat[128*128] (Minv, later V) + sRhs[64*129] + sCnt[256]
// ============================================================================
__global__ __launch_bounds__(NTHREADS, 1) void k_admm(const float* __restrict__ gV,
                                                      float* __restrict__ gOut) {
    extern __shared__ float smem[];
    float* sMat = smem;              // 128*128
    float* sRhs = smem + 16384;      // 64*129
    float* sCnt = sRhs + ROWS * 129; // 256
    const int blk = blockIdx.x;
    const int b = blk >> 5;
    const int row0 = (blk & 31) * ROWS;
    const int t = threadIdx.x;
    const int r = t & 63;
    const int iq = t >> 6;
    const int i0 = iq * 32;

    for (int idx = t; idx < 16384; idx += NTHREADS)
        sMat[idx] = gMinv[b * 16384 + idx];

    float z[32], u[32], Pr[32];
    const float* pp = gP + (b * NN + row0 + r) * 128 + i0;
#pragma unroll
    for (int e = 0; e < 32; e++) { z[e] = 0.0f; u[e] = 0.0f; Pr[e] = pp[e]; }

    for (int it = 0; it < ITERS; it++) {
        __syncthreads();   // prev-iter matmul reads of sRhs done (and sMat ready on iter 0)
#pragma unroll
        for (int e = 0; e < 32; e++)
            sRhs[r * 129 + i0 + e] = (z[e] - u[e]) - Pr[e];   // RHO = 1
        __syncthreads();

        unsigned long long acc[16];
#pragma unroll
        for (int q = 0; q < 16; q++) acc[q] = 0ULL;
#pragma unroll 8
        for (int j = 0; j < 128; j++) {
            unsigned long long rv2 = pack2(sRhs[r * 129 + j]);
            const ulonglong2* pm = (const ulonglong2*)(sMat + j * 128 + i0);
#pragma unroll
            for (int q = 0; q < 8; q++) {
                ulonglong2 mv = pm[q];
                acc[2 * q] = ffma2(mv.x, rv2, acc[2 * q]);
                acc[2 * q + 1] = ffma2(mv.y, rv2, acc[2 * q + 1]);
            }
        }
        // pointwise z/u updates (registers only)
#pragma unroll
        for (int q = 0; q < 16; q++) {
            float2 xv = unpack2(acc[q]);
            float xu0 = xv.x + u[2 * q];
            float zn0 = fminf(fmaxf(xu0, 0.0f), 1.0f);
            u[2 * q] = xu0 - zn0;
            z[2 * q] = zn0;
            float xu1 = xv.y + u[2 * q + 1];
            float zn1 = fminf(fmaxf(xu1, 0.0f), 1.0f);
            u[2 * q + 1] = xu1 - zn1;
            z[2 * q + 1] = zn1;
        }
    }
    __syncthreads();

    // epilogue: overwrite sMat with V; threshold + row counts
    for (int idx = t; idx < 16384; idx += NTHREADS)
        sMat[idx] = gV[b * 16384 + idx];
    float cp = 0.0f;
#pragma unroll
    for (int e = 0; e < 32; e++) cp += (z[e] > 0.5f) ? 1.0f : 0.0f;
    sCnt[r * 4 + iq] = cp;
    __syncthreads();

    float cnt = sCnt[r * 4] + sCnt[r * 4 + 1] + sCnt[r * 4 + 2] + sCnt[r * 4 + 3];
    float inv = 1.0f / (128.0f * (cnt + 1e-10f));  // folds the V/m scaling
#pragma unroll
    for (int e = 0; e < 32; e++)
        sRhs[r * 129 + i0 + e] = (z[e] > 0.5f) ? inv : 0.0f;
    __syncthreads();

    // out[r][d] = sum_m coeff[r][m] * V[m][d]
    unsigned long long acc[16];
#pragma unroll
    for (int q = 0; q < 16; q++) acc[q] = 0ULL;
#pragma unroll 4
    for (int mi = 0; mi < 128; mi++) {
        unsigned long long c2 = pack2(sRhs[r * 129 + mi]);
        const ulonglong2* pm = (const ulonglong2*)(sMat + mi * 128 + i0);
#pragma unroll
        for (int q = 0; q < 8; q++) {
            ulonglong2 mv = pm[q];
            acc[2 * q] = ffma2(mv.x, c2, acc[2 * q]);
            acc[2 * q + 1] = ffma2(mv.y, c2, acc[2 * q + 1]);
        }
    }
    float* op = gOut + (b * NN + row0 + r) * 128 + i0;
#pragma unroll
    for (int q = 0; q < 16; q++) {
        float2 v = unpack2(acc[q]);
        op[2 * q] = v.x;
        op[2 * q + 1] = v.y;
    }
}

// ============================================================================

extern "C" void kernel_launch(void* const* d_in, const int* in_sizes, int n_in,
                              void* d_out, int out_size) {
    const float* gQ = (const float*)d_in[0];
    const float* gV = (const float*)d_in[1];
    // defensive: identify by element counts (Q: 8*2048*128, V: 8*128*128)
    if (n_in >= 2 && in_sizes[0] == BB * MM * DD && in_sizes[1] == BB * NN * DD) {
        gV = (const float*)d_in[0];
        gQ = (const float*)d_in[1];
    }
    float* out = (float*)d_out;

    const int SMEM1 = (2 * 128 * 129 + 128) * 4;           // 132608
    const int SMEM2 = (128 * 128 + ROWS * 129) * 4;        // 98560
    const int SMEM3 = (128 * 128 + ROWS * 129 + 256) * 4;  // 99584

    cudaFuncSetAttribute(k_minv, cudaFuncAttributeMaxDynamicSharedMemorySize, SMEM1);
    cudaFuncSetAttribute(k_prep, cudaFuncAttributeMaxDynamicSharedMemorySize, SMEM2);
    cudaFuncSetAttribute(k_admm, cudaFuncAttributeMaxDynamicSharedMemorySize, SMEM3);

    k_minv<<<BB, NTHREADS, SMEM1>>>(gV);
    k_prep<<<BB * (NN / ROWS), NTHREADS, SMEM2>>>(gQ, gV);
    k_admm<<<BB * (NN / ROWS), NTHREADS, SMEM3>>>(gV, out);
}

// round 2
// speedup vs baseline: 1.1813x; 1.1813x over previous
#include <cuda_runtime.h>

#define BB 8
#define NN 2048
#define ITERS 50
#define ROWS 64

// scratch (allocation-free rule: __device__ global)
__device__ float gMinv[BB * 128 * 128];   // 512 KB

// ---- packed f32x2 helpers (ptxas won't emit FFMA2 from C++) ----
__device__ __forceinline__ unsigned long long ffma2(unsigned long long a,
                                                    unsigned long long b,
                                                    unsigned long long c) {
    unsigned long long d;
    asm("fma.rn.f32x2 %0, %1, %2, %3;" : "=l"(d) : "l"(a), "l"(b), "l"(c));
    return d;
}
__device__ __forceinline__ unsigned long long pack2(float x) {
    union { unsigned long long u; float2 f; } c;
    c.f = make_float2(x, x);
    return c.u;
}
__device__ __forceinline__ float2 unpack2(unsigned long long v) {
    union { unsigned long long u; float2 f; } c;
    c.u = v;
    return c.f;
}

// ============================================================================
// Kernel 1: Minv = (I + E)^-1 via 7-step Neumann-Horner, E = (2/m^2) V V^T.
// ||E|| <= ~0.0655 -> truncation error ||E||^8/(1-||E||) ~ 3e-10 (<< fp32 eps).
// grid 8 (1 CTA/batch) x 1024 threads.
// smem: sVt[128*132] ([d][m], padded) + sEA[128*129] (A-layout) + sY[128*128]
// ============================================================================
__global__ __launch_bounds__(1024, 1) void k_minv(const float* __restrict__ gV) {
    extern __shared__ float smem[];
    float* sVt = smem;                  // 128*132
    float* sEA = smem + 128 * 132;      // 128*129 (stride 129: conflict-free scalar col reads)
    float* sY  = sEA + 128 * 129;       // 128*128 (stride 128: aligned LDS.128 broadcast)
    const int b = blockIdx.x;
    const int t = threadIdx.x;

    // transposed load: V[m][d] -> sVt[d][m] (stride 132: 16B-aligned rows, 4-way STS conflict ok)
    for (int idx = t; idx < 16384; idx += 1024) {
        int m = idx >> 7, d = idx & 127;
        sVt[d * 132 + m] = gV[b * 16384 + idx];
    }
    __syncthreads();

    const int r = t & 127;
    const int i0 = (t >> 7) * 16;

    // E[r][i] = (1/8192) * sum_d Vt[d][r] * Vt[d][i]
    {
        unsigned long long acc[8];
#pragma unroll
        for (int e = 0; e < 8; e++) acc[e] = 0ULL;
#pragma unroll 8
        for (int d = 0; d < 128; d++) {
            unsigned long long a2 = pack2(sVt[d * 132 + r]);
            const ulonglong2* pm = (const ulonglong2*)(sVt + d * 132 + i0);
#pragma unroll
            for (int q = 0; q < 4; q++) {
                ulonglong2 mv = pm[q];
                acc[2 * q]     = ffma2(mv.x, a2, acc[2 * q]);
                acc[2 * q + 1] = ffma2(mv.y, a2, acc[2 * q + 1]);
            }
        }
        const float sc = 1.0f / 8192.0f;
#pragma unroll
        for (int e = 0; e < 8; e++) {
            float2 v = unpack2(acc[e]);
            sEA[r * 129 + i0 + 2 * e]     = sc * v.x;
            sEA[r * 129 + i0 + 2 * e + 1] = sc * v.y;
        }
    }
    __syncthreads();

    // Y = I - E
    for (int idx = t; idx < 16384; idx += 1024) {
        int i = idx >> 7, j = idx & 127;
        sY[idx] = ((i == j) ? 1.0f : 0.0f) - sEA[i * 129 + j];
    }
    __syncthreads();

    // 7x: Y <- I - E*Y   (final degree-8 Neumann polynomial... degree 1+7 = 8 terms)
    for (int step = 0; step < 7; step++) {
        unsigned long long acc[8];
#pragma unroll
        for (int e = 0; e < 8; e++) acc[e] = 0ULL;
#pragma unroll 8
        for (int d = 0; d < 128; d++) {
            unsigned long long a2 = pack2(sEA[r * 129 + d]);
            const ulonglong2* pm = (const ulonglong2*)(sY + d * 128 + i0);
#pragma unroll
            for (int q = 0; q < 4; q++) {
                ulonglong2 mv = pm[q];
                acc[2 * q]     = ffma2(mv.x, a2, acc[2 * q]);
                acc[2 * q + 1] = ffma2(mv.y, a2, acc[2 * q + 1]);
            }
        }
        __syncthreads();   // all reads of sY complete before in-place overwrite
#pragma unroll
        for (int e = 0; e < 8; e++) {
            float2 v = unpack2(acc[e]);
            int c0 = i0 + 2 * e;
            sY[r * 128 + c0]     = ((r == c0)     ? 1.0f : 0.0f) - v.x;
            sY[r * 128 + c0 + 1] = ((r == c0 + 1) ? 1.0f : 0.0f) - v.y;
        }
        __syncthreads();
    }

    for (int idx = t; idx < 16384; idx += 1024)
        gMinv[b * 16384 + idx] = sY[idx];
}

// ============================================================================
// Kernel 2 (fused): P prep + 50 ADMM iterations + threshold + output GEMM.
// grid 256 (b*32 + tile), 512 threads. Thread owns (row r, 16 i's).
// z, u, P live in registers for all 50 iterations.
// smem: sMat[128*132] (Vt for P phase / Minv / V) + sRhs[64*129] + sCnt[512]
// ============================================================================
__global__ __launch_bounds__(512, 1) void k_admm(const float* __restrict__ gQ,
                                                 const float* __restrict__ gV,
                                                 float* __restrict__ gOut) {
    extern __shared__ float smem[];
    float* sMat = smem;                    // 128*132 region (stride 132 in P phase, 128 after)
    float* sRhs = smem + 128 * 132;        // 64*129
    float* sCnt = sRhs + ROWS * 129;       // 512
    const int blk = blockIdx.x;
    const int b = blk >> 5;
    const int row0 = (blk & 31) * ROWS;
    const int t = threadIdx.x;
    const int r = t & 63;
    const int iq = t >> 6;                 // 0..7
    const int i0 = iq * 16;

    // ---- Phase P: load Vt (transposed, stride 132) + Q rows, compute P in regs ----
    for (int idx = t; idx < 16384; idx += 512) {
        int m = idx >> 7, d = idx & 127;
        sMat[d * 132 + m] = gV[b * 16384 + idx];
    }
    for (int idx = t; idx < ROWS * 128; idx += 512) {
        int rl = idx >> 7, d = idx & 127;
        sRhs[rl * 129 + d] = gQ[(b * NN + row0 + rl) * 128 + d];
    }
    __syncthreads();

    float z[16], u[16], Pr[16];
    {
        unsigned long long acc[8];
#pragma unroll
        for (int e = 0; e < 8; e++) acc[e] = 0ULL;
#pragma unroll 8
        for (int d = 0; d < 128; d++) {
            unsigned long long q2 = pack2(sRhs[r * 129 + d]);
            const ulonglong2* pm = (const ulonglong2*)(sMat + d * 132 + i0);
#pragma unroll
            for (int q = 0; q < 4; q++) {
                ulonglong2 mv = pm[q];
                acc[2 * q]     = ffma2(mv.x, q2, acc[2 * q]);
                acc[2 * q + 1] = ffma2(mv.y, q2, acc[2 * q + 1]);
            }
        }
        const float cP = -2.0f / 128.0f;
        const float cL = 0.1f / 128.0f;
#pragma unroll
        for (int e = 0; e < 8; e++) {
            float2 v = unpack2(acc[e]);
            Pr[2 * e]     = cP * v.x + cL;
            Pr[2 * e + 1] = cP * v.y + cL;
        }
    }
#pragma unroll
    for (int e = 0; e < 16; e++) { z[e] = 0.0f; u[e] = 0.0f; }
    __syncthreads();   // P-phase reads of sMat done

    // ---- load Minv (stride 128) ----
    for (int idx = t; idx < 16384; idx += 512)
        sMat[idx] = gMinv[b * 16384 + idx];

    // ---- 50 ADMM iterations ----
    for (int it = 0; it < ITERS; it++) {
#pragma unroll
        for (int e = 0; e < 16; e++)
            sRhs[r * 129 + i0 + e] = (z[e] - u[e]) - Pr[e];   // RHO = 1
        __syncthreads();   // also covers Minv load on iter 0

        unsigned long long acc[8];
#pragma unroll
        for (int e = 0; e < 8; e++) acc[e] = 0ULL;
#pragma unroll 8
        for (int j = 0; j < 128; j++) {
            unsigned long long rv2 = pack2(sRhs[r * 129 + j]);
            const ulonglong2* pm = (const ulonglong2*)(sMat + j * 128 + i0);
#pragma unroll
            for (int q = 0; q < 4; q++) {
                ulonglong2 mv = pm[q];
                acc[2 * q]     = ffma2(mv.x, rv2, acc[2 * q]);
                acc[2 * q + 1] = ffma2(mv.y, rv2, acc[2 * q + 1]);
            }
        }
        __syncthreads();   // all matmul reads of sRhs done before next-iter write

#pragma unroll
        for (int e = 0; e < 8; e++) {
            float2 xv = unpack2(acc[e]);
            float xu0 = xv.x + u[2 * e];
            float zn0 = fminf(fmaxf(xu0, 0.0f), 1.0f);
            u[2 * e] = xu0 - zn0;
            z[2 * e] = zn0;
            float xu1 = xv.y + u[2 * e + 1];
            float zn1 = fminf(fmaxf(xu1, 0.0f), 1.0f);
            u[2 * e + 1] = xu1 - zn1;
            z[2 * e + 1] = zn1;
        }
    }

    // ---- epilogue: sMat <- V (row-major), threshold + counts ----
    for (int idx = t; idx < 16384; idx += 512)
        sMat[idx] = gV[b * 16384 + idx];
    float cp = 0.0f;
#pragma unroll
    for (int e = 0; e < 16; e++) cp += (z[e] > 0.5f) ? 1.0f : 0.0f;
    sCnt[r * 8 + iq] = cp;
    __syncthreads();

    float cnt = 0.0f;
#pragma unroll
    for (int k = 0; k < 8; k++) cnt += sCnt[r * 8 + k];
    float inv = 1.0f / (128.0f * (cnt + 1e-10f));   // folds V/m scaling
#pragma unroll
    for (int e = 0; e < 16; e++)
        sRhs[r * 129 + i0 + e] = (z[e] > 0.5f) ? inv : 0.0f;
    __syncthreads();

    // out[r][i0..i0+15] = sum_m coeff[r][m] * V[m][d]
    unsigned long long acc[8];
#pragma unroll
    for (int e = 0; e < 8; e++) acc[e] = 0ULL;
#pragma unroll 8
    for (int mi = 0; mi < 128; mi++) {
        unsigned long long c2 = pack2(sRhs[r * 129 + mi]);
        const ulonglong2* pm = (const ulonglong2*)(sMat + mi * 128 + i0);
#pragma unroll
        for (int q = 0; q < 4; q++) {
            ulonglong2 mv = pm[q];
            acc[2 * q]     = ffma2(mv.x, c2, acc[2 * q]);
            acc[2 * q + 1] = ffma2(mv.y, c2, acc[2 * q + 1]);
        }
    }
    float* op = gOut + (b * NN + row0 + r) * 128 + i0;
#pragma unroll
    for (int q = 0; q < 4; q++) {
        ulonglong2 v = *(ulonglong2*)&acc[2 * q];
        float2 a = unpack2(v.x);
        float2 c = unpack2(v.y);
        ((float4*)op)[q] = make_float4(a.x, a.y, c.x, c.y);
    }
}

// ============================================================================

extern "C" void kernel_launch(void* const* d_in, const int* in_sizes, int n_in,
                              void* d_out, int out_size) {
    const float* gQ = (const float*)d_in[0];
    const float* gV = (const float*)d_in[1];
    if (n_in >= 2 && in_sizes[0] == BB * 128 * 128 && in_sizes[1] == BB * NN * 128) {
        gV = (const float*)d_in[0];
        gQ = (const float*)d_in[1];
    }
    float* out = (float*)d_out;

    const int SMEM_MINV = (128 * 132 + 128 * 129 + 128 * 128) * 4;   // 199168
    const int SMEM_ADMM = (128 * 132 + ROWS * 129 + 512) * 4;        // 102656

    cudaFuncSetAttribute(k_minv, cudaFuncAttributeMaxDynamicSharedMemorySize, SMEM_MINV);
    cudaFuncSetAttribute(k_admm, cudaFuncAttributeMaxDynamicSharedMemorySize, SMEM_ADMM);

    k_minv<<<BB, 1024, SMEM_MINV>>>(gV);
    k_admm<<<BB * (NN / ROWS), 512, SMEM_ADMM>>>(gQ, gV, out);
}